// round 3
// baseline (speedup 1.0000x reference)
#include <cuda_runtime.h>

#define N_ROWS (64 * 1024)
#define T_LEN  1200
#define WARPS_PER_BLOCK 8

// Scratch: per-row scalar feature (allowed: __device__ global, no allocation)
__device__ float g_feat[N_ROWS];

// ---------------------------------------------------------------------------
// Kernel 1: per-row temporal pipeline. One warp per row.
//   conv(k2,s2) -> pool3+relu -> conv(k4,s2,p1) -> pool2+relu
//   -> conv(k4,s2,p1) -> pool2+relu -> conv(k4,s2,p1) -> pool2+relu
//   -> conv(k3,s1) -> scalar
// Lengths: 1200 -> 600 -> 200 -> 100 -> 50 -> 25 -> 12 -> 6 -> 3 -> 1
// Stage 1+2 fused directly against global memory (relu(max3(conv)) reads
// 6 consecutive floats per output). Remaining stages in per-warp smem.
// ---------------------------------------------------------------------------
__global__ __launch_bounds__(WARPS_PER_BLOCK * 32)
void row_pipeline_kernel(
    const float* __restrict__ x,
    const float* __restrict__ c0_w, const float* __restrict__ c0_b,
    const float* __restrict__ c2_w, const float* __restrict__ c2_b,
    const float* __restrict__ c4_w, const float* __restrict__ c4_b,
    const float* __restrict__ c6_w, const float* __restrict__ c6_b,
    const float* __restrict__ c8_w, const float* __restrict__ c8_b)
{
    __shared__ float sA[WARPS_PER_BLOCK][200];
    __shared__ float sB[WARPS_PER_BLOCK][100];

    const int warp = threadIdx.x >> 5;
    const int lane = threadIdx.x & 31;
    const int row  = blockIdx.x * WARPS_PER_BLOCK + warp;
    if (row >= N_ROWS) return;

    const float* __restrict__ xr = x + (size_t)row * T_LEN;

    // --- Stage 0+1: conv(k=2,s=2) then maxpool3 then relu : 1200 -> 200 ---
    const float w00 = c0_w[0], w01 = c0_w[1], b0 = c0_b[0];
    float* h2 = sA[warp];
    #pragma unroll
    for (int it = 0; it < 7; ++it) {
        int j = lane + 32 * it;           // 7*32 = 224 >= 200
        if (j < 200) {
            // conv outputs 3j..3j+2 use x[6j .. 6j+5]; 8B-aligned float2 loads
            const float2* p = reinterpret_cast<const float2*>(xr + 6 * j);
            float2 a = p[0], b = p[1], c = p[2];
            float m0 = w00 * a.x + w01 * a.y;
            float m1 = w00 * b.x + w01 * b.y;
            float m2 = w00 * c.x + w01 * c.y;
            float m  = fmaxf(m0, fmaxf(m1, m2));
            h2[j] = fmaxf(m + b0, 0.0f);
        }
    }
    __syncwarp();

    // --- Stage 2: conv(k=4,s=2,p=1) : 200 -> 100 ---
    const float w20 = c2_w[0], w21 = c2_w[1], w22 = c2_w[2], w23 = c2_w[3], b2 = c2_b[0];
    float* y3 = sB[warp];
    #pragma unroll
    for (int it = 0; it < 4; ++it) {
        int i = lane + 32 * it;
        if (i < 100) {
            float v0 = (i == 0)        ? 0.0f : h2[2 * i - 1];
            float v1 = h2[2 * i];
            float v2 = h2[2 * i + 1];
            float v3 = (2 * i + 2 < 200) ? h2[2 * i + 2] : 0.0f;
            y3[i] = b2 + w20 * v0 + w21 * v1 + w22 * v2 + w23 * v3;
        }
    }
    __syncwarp();

    // --- Stage 3: maxpool2 + relu : 100 -> 50 (write into sA, h2 dead) ---
    float* h4 = sA[warp];
    #pragma unroll
    for (int it = 0; it < 2; ++it) {
        int i = lane + 32 * it;
        if (i < 50)
            h4[i] = fmaxf(fmaxf(y3[2 * i], y3[2 * i + 1]), 0.0f);
    }
    __syncwarp();

    // --- Stage 4: conv(k=4,s=2,p=1) : 50 -> 25 (write into sB, y3 dead) ---
    const float w40 = c4_w[0], w41 = c4_w[1], w42 = c4_w[2], w43 = c4_w[3], b4 = c4_b[0];
    float* y5 = sB[warp];
    if (lane < 25) {
        int i = lane;
        float v0 = (i == 0)       ? 0.0f : h4[2 * i - 1];
        float v1 = h4[2 * i];
        float v2 = h4[2 * i + 1];
        float v3 = (2 * i + 2 < 50) ? h4[2 * i + 2] : 0.0f;
        y5[i] = b4 + w40 * v0 + w41 * v1 + w42 * v2 + w43 * v3;
    }
    __syncwarp();

    // --- Stage 5: maxpool2 + relu : 25 -> 12 (last element dropped) ---
    float* h6 = sA[warp];
    if (lane < 12)
        h6[lane] = fmaxf(fmaxf(y5[2 * lane], y5[2 * lane + 1]), 0.0f);
    __syncwarp();

    // --- Stage 6: conv(k=4,s=2,p=1) : 12 -> 6 ---
    const float w60 = c6_w[0], w61 = c6_w[1], w62 = c6_w[2], w63 = c6_w[3], b6 = c6_b[0];
    float* y7 = sB[warp];
    if (lane < 6) {
        int i = lane;
        float v0 = (i == 0)       ? 0.0f : h6[2 * i - 1];
        float v1 = h6[2 * i];
        float v2 = h6[2 * i + 1];
        float v3 = (2 * i + 2 < 12) ? h6[2 * i + 2] : 0.0f;
        y7[i] = b6 + w60 * v0 + w61 * v1 + w62 * v2 + w63 * v3;
    }
    __syncwarp();

    // --- Stage 7: maxpool2 + relu : 6 -> 3 ---
    float* h8 = sA[warp];
    if (lane < 3)
        h8[lane] = fmaxf(fmaxf(y7[2 * lane], y7[2 * lane + 1]), 0.0f);
    __syncwarp();

    // --- Stage 8: conv(k=3,s=1,p=0) : 3 -> 1 ---
    if (lane == 0) {
        float f = c8_b[0] + c8_w[0] * h8[0] + c8_w[1] * h8[1] + c8_w[2] * h8[2];
        g_feat[row] = f;
    }
}

// ---------------------------------------------------------------------------
// Kernel 2: logits = feat @ cls_w^T + cls_b, softmax over 3 classes.
// One block per batch element.
// ---------------------------------------------------------------------------
__global__ __launch_bounds__(128)
void classify_kernel(const float* __restrict__ cls_w,
                     const float* __restrict__ cls_b,
                     float* __restrict__ out)
{
    const int b = blockIdx.x;
    const int t = threadIdx.x;

    const float* __restrict__ f = g_feat + b * 1024;
    float a0 = 0.f, a1 = 0.f, a2 = 0.f;
    #pragma unroll
    for (int n = t; n < 1024; n += 128) {
        float v = f[n];
        a0 += v * cls_w[n];
        a1 += v * cls_w[1024 + n];
        a2 += v * cls_w[2048 + n];
    }

    __shared__ float s0[128], s1[128], s2[128];
    s0[t] = a0; s1[t] = a1; s2[t] = a2;
    __syncthreads();
    #pragma unroll
    for (int off = 64; off > 0; off >>= 1) {
        if (t < off) {
            s0[t] += s0[t + off];
            s1[t] += s1[t + off];
            s2[t] += s2[t + off];
        }
        __syncthreads();
    }

    if (t == 0) {
        float l0 = s0[0] + cls_b[0];
        float l1 = s1[0] + cls_b[1];
        float l2 = s2[0] + cls_b[2];
        float m  = fmaxf(l0, fmaxf(l1, l2));
        float e0 = expf(l0 - m), e1 = expf(l1 - m), e2 = expf(l2 - m);
        float inv = 1.0f / (e0 + e1 + e2);
        out[b * 3 + 0] = e0 * inv;
        out[b * 3 + 1] = e1 * inv;
        out[b * 3 + 2] = e2 * inv;
    }
}

// ---------------------------------------------------------------------------
// Launch. Input order per metadata:
// 0:x 1:c0_w 2:c0_b 3:c2_w 4:c2_b 5:c4_w 6:c4_b 7:c6_w 8:c6_b 9:c8_w 10:c8_b
// 11:gcn1_w 12:gcn1_b 13:gcn2_w 14:gcn2_b (dead code, unused) 15:cls_w 16:cls_b
// ---------------------------------------------------------------------------
extern "C" void kernel_launch(void* const* d_in, const int* in_sizes, int n_in,
                              void* d_out, int out_size)
{
    const float* x    = (const float*)d_in[0];
    const float* c0_w = (const float*)d_in[1];
    const float* c0_b = (const float*)d_in[2];
    const float* c2_w = (const float*)d_in[3];
    const float* c2_b = (const float*)d_in[4];
    const float* c4_w = (const float*)d_in[5];
    const float* c4_b = (const float*)d_in[6];
    const float* c6_w = (const float*)d_in[7];
    const float* c6_b = (const float*)d_in[8];
    const float* c8_w = (const float*)d_in[9];
    const float* c8_b = (const float*)d_in[10];
    const float* cls_w = (const float*)d_in[15];
    const float* cls_b = (const float*)d_in[16];
    float* out = (float*)d_out;

    const int blocks = N_ROWS / WARPS_PER_BLOCK;  // 8192
    row_pipeline_kernel<<<blocks, WARPS_PER_BLOCK * 32>>>(
        x, c0_w, c0_b, c2_w, c2_b, c4_w, c4_b, c6_w, c6_b, c8_w, c8_b);
    classify_kernel<<<64, 128>>>(cls_w, cls_b, out);
}